// round 4
// baseline (speedup 1.0000x reference)
#include <cuda_runtime.h>

#define NN 100000
#define EE 1600000
#define LL 3
#define CAP 96

typedef unsigned long long ull;

// ---------------- device scratch ----------------------------------------------
__device__ float g_h[NN * 64];
__device__ float g_z1[NN * 64];
__device__ float g_z2[NN * 64];
__device__ float g_stats[LL * 256];   // per layer: [sum1(64) sq1(64) sum2(64) sq2(64)]
__device__ int   g_deg[NN];
__device__ int   g_csr[(size_t)NN * CAP];

// ---------------- packed f32x2 helpers ----------------------------------------
__device__ __forceinline__ ull pack2(float a, float b) {
    ull r;
    asm("mov.b64 %0, {%1, %2};" : "=l"(r) : "f"(a), "f"(b));
    return r;
}
__device__ __forceinline__ float2 unpack2(ull v) {
    float2 r;
    asm("mov.b64 {%0, %1}, %2;" : "=f"(r.x), "=f"(r.y) : "l"(v));
    return r;
}
__device__ __forceinline__ void ffma2(ull& d, ull a, ull b) {
    asm("fma.rn.f32x2 %0, %1, %2, %0;" : "+l"(d) : "l"(a), "l"(b));
}

// ---------------- zero degree + stats -----------------------------------------
__global__ void __launch_bounds__(1024) kzero() {
    int t = blockIdx.x * 1024 + threadIdx.x;
    if (t < NN) g_deg[t] = 0;
    if (t < LL * 256) g_stats[t] = 0.f;
}

// ---------------- CSR fill: bucket srcs by dst --------------------------------
__global__ void __launch_bounds__(256) kfill(const int* __restrict__ ei) {
    int e = blockIdx.x * 256 + threadIdx.x;
    if (e >= EE) return;
    int s = ei[e];
    int d = ei[EE + e];
    int pos = atomicAdd(&g_deg[d], 1);
    if (pos < CAP) g_csr[(size_t)d * CAP + pos] = s;
}

// ======== kA: gather + GEMM1 + stats1 (+ layer-0 classifier head) ==============
__global__ void __launch_bounds__(128, 3) kA(const float* __restrict__ x, int use_x,
                                             const float* __restrict__ W,
                                             const float* __restrict__ b,
                                             const float* __restrict__ fcW,
                                             const float* __restrict__ fcb,
                                             float* __restrict__ out, int layer) {
    __shared__ float Wsh[4096];
    __shared__ float zs[64 * 65];
    __shared__ float fw0[640];
    __shared__ float bs[64];
    __shared__ float bsum[10];
    int tid = threadIdx.x;
    for (int i = tid; i < 4096; i += 128) Wsh[i] = W[i];
    if (layer == 0) {
        for (int i = tid; i < 640; i += 128) fw0[i] = fcW[i];
        if (tid < 10) {
            float s = 0.f;
            for (int l = 0; l < LL + 1; l++) s += fcb[l * 10 + tid];
            bsum[tid] = s;
        }
    }
    if (tid < 64) bs[tid] = b[tid];
    __syncthreads();

    int n = blockIdx.x * 128 + tid;
    bool valid = n < NN;
    const float* hin = use_x ? x : g_h;

    float y[64];
    float head[10];
    if (valid) {
        // own row
        const float4* r = ((const float4*)hin) + (size_t)n * 16;
#pragma unroll
        for (int kk = 0; kk < 16; kk++) {
            float4 v = r[kk];
            y[4 * kk + 0] = v.x; y[4 * kk + 1] = v.y;
            y[4 * kk + 2] = v.z; y[4 * kk + 3] = v.w;
        }
        if (layer == 0) {
            // classifier head on raw x (y == x row right now)
#pragma unroll
            for (int c = 0; c < 10; c++) head[c] = bsum[c];
#pragma unroll
            for (int k = 0; k < 64; k++) {
                float v = y[k];
                const float* r0 = fw0 + k * 10;
#pragma unroll
                for (int c = 0; c < 10; c++) head[c] += v * r0[c];
            }
        }
        // gather neighbors
        int deg = g_deg[n];
        if (deg > CAP) deg = CAP;
        const int* adj = g_csr + (size_t)n * CAP;
        for (int e = 0; e < deg; e++) {
            const float4* rr = ((const float4*)hin) + (size_t)adj[e] * 16;
#pragma unroll
            for (int kk = 0; kk < 16; kk++) {
                float4 v = rr[kk];
                y[4 * kk + 0] += v.x; y[4 * kk + 1] += v.y;
                y[4 * kk + 2] += v.z; y[4 * kk + 3] += v.w;
            }
        }
    } else {
#pragma unroll
        for (int k = 0; k < 64; k++) y[k] = 0.f;
    }

    // GEMM: z1 = y @ W + b
    ull acc[32];
#pragma unroll
    for (int j = 0; j < 32; j++) acc[j] = pack2(bs[2 * j], bs[2 * j + 1]);
    const ulonglong2* Wv = (const ulonglong2*)Wsh;
#pragma unroll
    for (int k = 0; k < 64; k++) {
        ull a2 = pack2(y[k], y[k]);
        const ulonglong2* row = Wv + k * 16;
#pragma unroll
        for (int jj = 0; jj < 16; jj++) {
            ulonglong2 w = row[jj];
            ffma2(acc[2 * jj], a2, w.x);
            ffma2(acc[2 * jj + 1], a2, w.y);
        }
    }

    if (valid) {
        float4* o = ((float4*)g_z1) + (size_t)n * 16;
#pragma unroll
        for (int m = 0; m < 16; m++) {
            float2 lo = unpack2(acc[2 * m]);
            float2 hi = unpack2(acc[2 * m + 1]);
            o[m] = make_float4(lo.x, lo.y, hi.x, hi.y);
        }
        if (layer == 0) {
#pragma unroll
            for (int c = 0; c < 10; c++) out[n * 10 + c] = head[c];
        }
    }

    // stats1 via two-pass smem transpose (rows 0-63, then 64-127)
    int c = tid & 63;
    int hh = tid >> 6;
    float s_acc = 0.f, q_acc = 0.f;
#pragma unroll
    for (int p = 0; p < 2; p++) {
        __syncthreads();
        if ((tid >> 6) == p) {
            int rr = tid & 63;
#pragma unroll
            for (int m = 0; m < 32; m++) {
                float2 v = unpack2(acc[m]);
                zs[(2 * m) * 65 + rr] = valid ? v.x : 0.f;
                zs[(2 * m + 1) * 65 + rr] = valid ? v.y : 0.f;
            }
        }
        __syncthreads();
#pragma unroll
        for (int i = 0; i < 32; i++) {
            float v = zs[c * 65 + hh * 32 + i];
            s_acc += v;
            q_acc += v * v;
        }
    }
    atomicAdd(&g_stats[layer * 256 + c], s_acc);
    atomicAdd(&g_stats[layer * 256 + 64 + c], q_acc);
}

// ======== kB: BN1 + ReLU + GEMM2 + stats2 ======================================
__global__ void __launch_bounds__(128, 3) kB(const float* __restrict__ W,
                                             const float* __restrict__ b,
                                             const float* __restrict__ gam,
                                             const float* __restrict__ bet,
                                             int layer) {
    __shared__ float Wsh[4096];
    __shared__ float zs[64 * 65];
    __shared__ float bs[64], sA[64], sB[64];
    int tid = threadIdx.x;
    for (int i = tid; i < 4096; i += 128) Wsh[i] = W[i];
    if (tid < 64) {
        float s = g_stats[layer * 256 + tid];
        float q = g_stats[layer * 256 + 64 + tid];
        float mu = s * (1.f / NN);
        float var = q * (1.f / NN) - mu * mu;
        float a = rsqrtf(var + 1e-5f) * gam[tid];
        sA[tid] = a;
        sB[tid] = bet[tid] - mu * a;
        bs[tid] = b[tid];
    }
    __syncthreads();

    int n = blockIdx.x * 128 + tid;
    bool valid = n < NN;

    float y[64];
    if (valid) {
        const float4* r = ((const float4*)g_z1) + (size_t)n * 16;
#pragma unroll
        for (int kk = 0; kk < 16; kk++) {
            float4 v = r[kk];
            int k0 = 4 * kk;
            y[k0 + 0] = fmaxf(fmaf(v.x, sA[k0 + 0], sB[k0 + 0]), 0.f);
            y[k0 + 1] = fmaxf(fmaf(v.y, sA[k0 + 1], sB[k0 + 1]), 0.f);
            y[k0 + 2] = fmaxf(fmaf(v.z, sA[k0 + 2], sB[k0 + 2]), 0.f);
            y[k0 + 3] = fmaxf(fmaf(v.w, sA[k0 + 3], sB[k0 + 3]), 0.f);
        }
    } else {
#pragma unroll
        for (int k = 0; k < 64; k++) y[k] = 0.f;
    }

    ull acc[32];
#pragma unroll
    for (int j = 0; j < 32; j++) acc[j] = pack2(bs[2 * j], bs[2 * j + 1]);
    const ulonglong2* Wv = (const ulonglong2*)Wsh;
#pragma unroll
    for (int k = 0; k < 64; k++) {
        ull a2 = pack2(y[k], y[k]);
        const ulonglong2* row = Wv + k * 16;
#pragma unroll
        for (int jj = 0; jj < 16; jj++) {
            ulonglong2 w = row[jj];
            ffma2(acc[2 * jj], a2, w.x);
            ffma2(acc[2 * jj + 1], a2, w.y);
        }
    }

    if (valid) {
        float4* o = ((float4*)g_z2) + (size_t)n * 16;
#pragma unroll
        for (int m = 0; m < 16; m++) {
            float2 lo = unpack2(acc[2 * m]);
            float2 hi = unpack2(acc[2 * m + 1]);
            o[m] = make_float4(lo.x, lo.y, hi.x, hi.y);
        }
    }

    int c = tid & 63;
    int hh = tid >> 6;
    float s_acc = 0.f, q_acc = 0.f;
#pragma unroll
    for (int p = 0; p < 2; p++) {
        __syncthreads();
        if ((tid >> 6) == p) {
            int rr = tid & 63;
#pragma unroll
            for (int m = 0; m < 32; m++) {
                float2 v = unpack2(acc[m]);
                zs[(2 * m) * 65 + rr] = valid ? v.x : 0.f;
                zs[(2 * m + 1) * 65 + rr] = valid ? v.y : 0.f;
            }
        }
        __syncthreads();
#pragma unroll
        for (int i = 0; i < 32; i++) {
            float v = zs[c * 65 + hh * 32 + i];
            s_acc += v;
            q_acc += v * v;
        }
    }
    atomicAdd(&g_stats[layer * 256 + 128 + c], s_acc);
    atomicAdd(&g_stats[layer * 256 + 192 + c], q_acc);
}

// ======== kC: BN2+ReLU -> h; logits += h @ fcW[layer+1]; optional softmax ======
__global__ void __launch_bounds__(256) kC(const float* __restrict__ gam,
                                          const float* __restrict__ bet,
                                          const float* __restrict__ fcW,
                                          int layer, int final_layer,
                                          float* __restrict__ out) {
    __shared__ float fw[640];
    __shared__ float sA[64], sB[64];
    int tid = threadIdx.x;
    const float* fsrc = fcW + (layer + 1) * 640;
    for (int i = tid; i < 640; i += 256) fw[i] = fsrc[i];
    if (tid < 64) {
        float s = g_stats[layer * 256 + 128 + tid];
        float q = g_stats[layer * 256 + 192 + tid];
        float mu = s * (1.f / NN);
        float var = q * (1.f / NN) - mu * mu;
        float a = rsqrtf(var + 1e-5f) * gam[tid];
        sA[tid] = a;
        sB[tid] = bet[tid] - mu * a;
    }
    __syncthreads();
    int n = blockIdx.x * 256 + tid;
    if (n >= NN) return;
    float o[10];
#pragma unroll
    for (int c = 0; c < 10; c++) o[c] = out[n * 10 + c];
    const float4* z4 = ((const float4*)g_z2) + (size_t)n * 16;
    float4* hout = ((float4*)g_h) + (size_t)n * 16;
#pragma unroll
    for (int kk = 0; kk < 16; kk++) {
        float4 v = z4[kk];
        int k0 = kk * 4;
        float h0 = fmaxf(fmaf(v.x, sA[k0 + 0], sB[k0 + 0]), 0.f);
        float h1 = fmaxf(fmaf(v.y, sA[k0 + 1], sB[k0 + 1]), 0.f);
        float h2 = fmaxf(fmaf(v.z, sA[k0 + 2], sB[k0 + 2]), 0.f);
        float h3 = fmaxf(fmaf(v.w, sA[k0 + 3], sB[k0 + 3]), 0.f);
        if (!final_layer) hout[kk] = make_float4(h0, h1, h2, h3);
        const float* r0 = fw + k0 * 10;
#pragma unroll
        for (int c = 0; c < 10; c++)
            o[c] += h0 * r0[c] + h1 * r0[10 + c] + h2 * r0[20 + c] + h3 * r0[30 + c];
    }
    if (final_layer) {
        float m = -1e30f;
#pragma unroll
        for (int c = 0; c < 10; c++) m = fmaxf(m, o[c]);
        float s = 0.f;
#pragma unroll
        for (int c = 0; c < 10; c++) s += expf(o[c] - m);
        float lse = m + logf(s);
#pragma unroll
        for (int c = 0; c < 10; c++) o[c] -= lse;
    }
#pragma unroll
    for (int c = 0; c < 10; c++) out[n * 10 + c] = o[c];
}

// ---------------- launch --------------------------------------------------------
extern "C" void kernel_launch(void* const* d_in, const int* in_sizes, int n_in,
                              void* d_out, int out_size) {
    const float* x   = (const float*)d_in[0];
    const int*   ei  = (const int*)d_in[1];
    const float* W1  = (const float*)d_in[2];
    const float* b1  = (const float*)d_in[3];
    const float* g1  = (const float*)d_in[4];
    const float* be1 = (const float*)d_in[5];
    const float* W2  = (const float*)d_in[6];
    const float* b2  = (const float*)d_in[7];
    const float* gbn = (const float*)d_in[8];
    const float* bbn = (const float*)d_in[9];
    const float* fcW = (const float*)d_in[10];
    const float* fcb = (const float*)d_in[11];
    float* out = (float*)d_out;

    const int AB = (NN + 127) / 128;   // 782
    const int CB = (NN + 255) / 256;   // 391

    kzero<<<(NN + 1023) / 1024, 1024>>>();
    kfill<<<(EE + 255) / 256, 256>>>(ei);
    for (int l = 0; l < LL; l++) {
        int use_x = (l == 0) ? 1 : 0;
        kA<<<AB, 128>>>(x, use_x, W1 + l * 4096, b1 + l * 64, fcW, fcb, out, l);
        kB<<<AB, 128>>>(W2 + l * 4096, b2 + l * 64, g1 + l * 64, be1 + l * 64, l);
        kC<<<CB, 256>>>(gbn + l * 64, bbn + l * 64, fcW, l, (l == LL - 1) ? 1 : 0, out);
    }
}

// round 5
// speedup vs baseline: 1.2932x; 1.2932x over previous
#include <cuda_runtime.h>

#define NN 100000
#define EE 1600000
#define LL 3
#define CAP 96
#define NPB 64                      // nodes per block in kA/kB
#define PAD 68                      // y_s row stride (floats), 16B-aligned

typedef unsigned long long ull;

// ---------------- device scratch ----------------------------------------------
__device__ float g_h[NN * 64];
__device__ float g_z1[NN * 64];
__device__ float g_z2[NN * 64];
__device__ float g_stats[LL * 256];   // per layer: [sum1 sq1 sum2 sq2] x 64
__device__ int   g_deg[NN];
__device__ int   g_csr[(size_t)NN * CAP];

// ---------------- packed f32x2 helpers ----------------------------------------
__device__ __forceinline__ ull pack2(float a, float b) {
    ull r;
    asm("mov.b64 %0, {%1, %2};" : "=l"(r) : "f"(a), "f"(b));
    return r;
}
__device__ __forceinline__ float2 unpack2(ull v) {
    float2 r;
    asm("mov.b64 {%0, %1}, %2;" : "=f"(r.x), "=f"(r.y) : "l"(v));
    return r;
}
__device__ __forceinline__ void ffma2(ull& d, ull a, ull b) {
    asm("fma.rn.f32x2 %0, %1, %2, %0;" : "+l"(d) : "l"(a), "l"(b));
}

// ---------------- zero degree + stats -----------------------------------------
__global__ void __launch_bounds__(1024) kzero() {
    int t = blockIdx.x * 1024 + threadIdx.x;
    if (t < NN) g_deg[t] = 0;
    if (t < LL * 256) g_stats[t] = 0.f;
}

// ---------------- CSR fill ------------------------------------------------------
__global__ void __launch_bounds__(256) kfill(const int* __restrict__ ei) {
    int e = blockIdx.x * 256 + threadIdx.x;
    if (e >= EE) return;
    int s = ei[e];
    int d = ei[EE + e];
    int pos = atomicAdd(&g_deg[d], 1);
    if (pos < CAP) g_csr[(size_t)d * CAP + pos] = s;
}

// ---------------- kinit: logits = x @ fcW[0] + sum_l fcb[l] --------------------
__global__ void __launch_bounds__(256) kinit(const float* __restrict__ x,
                                             const float* __restrict__ fcW,
                                             const float* __restrict__ fcb,
                                             float* __restrict__ out) {
    __shared__ float fw[640];
    __shared__ float bsum[10];
    int tid = threadIdx.x;
    for (int i = tid; i < 640; i += 256) fw[i] = fcW[i];
    if (tid < 10) {
        float b = 0.f;
        for (int l = 0; l < LL + 1; l++) b += fcb[l * 10 + tid];
        bsum[tid] = b;
    }
    __syncthreads();
    int n = blockIdx.x * 256 + tid;
    if (n >= NN) return;
    float acc[10];
#pragma unroll
    for (int c = 0; c < 10; c++) acc[c] = bsum[c];
    const float4* x4 = ((const float4*)x) + (size_t)n * 16;
#pragma unroll
    for (int kk = 0; kk < 16; kk++) {
        float4 v = x4[kk];
        const float* r0 = fw + (kk * 4) * 10;
#pragma unroll
        for (int c = 0; c < 10; c++)
            acc[c] += v.x * r0[c] + v.y * r0[10 + c] + v.z * r0[20 + c] + v.w * r0[30 + c];
    }
#pragma unroll
    for (int c = 0; c < 10; c++) out[n * 10 + c] = acc[c];
}

// ---- shared GEMM tail: y_s(64xNPB, k-major) @ Wsh(64x64) + bias ----------------
// thread tile: 4 nodes (t&15) x 4 cols (t>>4); acc packed as node-pairs (f32x2)
__device__ __forceinline__ void gemm_tile(const float* y_s, const float* Wsh,
                                          const float* bs, int cg, int ng,
                                          ull acc[4][2]) {
#pragma unroll
    for (int c = 0; c < 4; c++) {
        float b = bs[4 * cg + c];
        acc[c][0] = pack2(b, b);
        acc[c][1] = acc[c][0];
    }
#pragma unroll 8
    for (int k = 0; k < 64; k++) {
        ulonglong2 a2 = ((const ulonglong2*)(y_s + k * PAD))[ng];
        float4 w = *(const float4*)(Wsh + k * 64 + cg * 4);
        ull w0 = pack2(w.x, w.x);
        ull w1 = pack2(w.y, w.y);
        ull w2 = pack2(w.z, w.z);
        ull w3 = pack2(w.w, w.w);
        ffma2(acc[0][0], a2.x, w0); ffma2(acc[0][1], a2.y, w0);
        ffma2(acc[1][0], a2.x, w1); ffma2(acc[1][1], a2.y, w1);
        ffma2(acc[2][0], a2.x, w2); ffma2(acc[2][1], a2.y, w2);
        ffma2(acc[3][0], a2.x, w3); ffma2(acc[3][1], a2.y, w3);
    }
}

// ---- shared epilogue: unpack, store z, shfl-reduce stats, atomics --------------
__device__ __forceinline__ void store_stats(ull acc[4][2], float* zout, int base,
                                            int ng, int cg, int lane,
                                            float* stat_s, float* stat_q) {
    float val[4][4];  // [c][node i]
#pragma unroll
    for (int c = 0; c < 4; c++) {
        float2 lo = unpack2(acc[c][0]);
        float2 hi = unpack2(acc[c][1]);
        val[c][0] = lo.x; val[c][1] = lo.y; val[c][2] = hi.x; val[c][3] = hi.y;
    }
    float s[4] = {0.f, 0.f, 0.f, 0.f};
    float q[4] = {0.f, 0.f, 0.f, 0.f};
#pragma unroll
    for (int i = 0; i < 4; i++) {
        int n = base + 4 * ng + i;
        if (n < NN) {
            float4 o = make_float4(val[0][i], val[1][i], val[2][i], val[3][i]);
            *(float4*)(zout + (size_t)n * 64 + 4 * cg) = o;
#pragma unroll
            for (int c = 0; c < 4; c++) {
                float v = val[c][i];
                s[c] += v;
                q[c] += v * v;
            }
        }
    }
#pragma unroll
    for (int off = 8; off >= 1; off >>= 1) {
#pragma unroll
        for (int c = 0; c < 4; c++) {
            s[c] += __shfl_xor_sync(0xffffffffu, s[c], off);
            q[c] += __shfl_xor_sync(0xffffffffu, q[c], off);
        }
    }
    if ((lane & 15) == 0) {
#pragma unroll
        for (int c = 0; c < 4; c++) {
            atomicAdd(&stat_s[4 * cg + c], s[c]);
            atomicAdd(&stat_q[4 * cg + c], q[c]);
        }
    }
}

// ======== kA: CSR gather -> smem(T) -> tiled GEMM1 -> z1 + stats1 ===============
__global__ void __launch_bounds__(256) kA(const float* __restrict__ x, int use_x,
                                          const float* __restrict__ W,
                                          const float* __restrict__ b, int layer) {
    __shared__ float y_s[64 * PAD];
    __shared__ float Wsh[4096];
    __shared__ float bs[64];
    int tid = threadIdx.x, lane = tid & 31, wid = tid >> 5;
    for (int i = tid; i < 4096; i += 256) Wsh[i] = W[i];
    if (tid < 64) bs[tid] = b[tid];
    const float* hin = use_x ? x : g_h;
    int base = blockIdx.x * NPB;

    // gather phase: warp wid handles nodes base + wid*8 .. +7, lane owns cols 2l,2l+1
#pragma unroll 1
    for (int i = 0; i < 8; i++) {
        int nl = wid * 8 + i;
        int n = base + nl;
        float sx = 0.f, sy = 0.f;
        if (n < NN) {
            float2 v = ((const float2*)(hin + (size_t)n * 64))[lane];
            sx = v.x; sy = v.y;
            int deg = g_deg[n];
            if (deg > CAP) deg = CAP;
            const int* adj = g_csr + (size_t)n * CAP;
            float a1x = 0.f, a1y = 0.f, a2x = 0.f, a2y = 0.f, a3x = 0.f, a3y = 0.f;
            int e = 0;
            for (; e + 4 <= deg; e += 4) {
                int i0 = adj[e], i1 = adj[e + 1], i2 = adj[e + 2], i3 = adj[e + 3];
                float2 v0 = ((const float2*)(hin + (size_t)i0 * 64))[lane];
                float2 v1 = ((const float2*)(hin + (size_t)i1 * 64))[lane];
                float2 v2 = ((const float2*)(hin + (size_t)i2 * 64))[lane];
                float2 v3 = ((const float2*)(hin + (size_t)i3 * 64))[lane];
                sx += v0.x; sy += v0.y;
                a1x += v1.x; a1y += v1.y;
                a2x += v2.x; a2y += v2.y;
                a3x += v3.x; a3y += v3.y;
            }
            for (; e < deg; e++) {
                float2 v0 = ((const float2*)(hin + (size_t)adj[e] * 64))[lane];
                sx += v0.x; sy += v0.y;
            }
            sx += (a1x + a2x) + a3x;
            sy += (a1y + a2y) + a3y;
        }
        y_s[(2 * lane) * PAD + nl] = sx;
        y_s[(2 * lane + 1) * PAD + nl] = sy;
    }
    __syncthreads();

    int ng = tid & 15, cg = tid >> 4;
    ull acc[4][2];
    gemm_tile(y_s, Wsh, bs, cg, ng, acc);
    store_stats(acc, g_z1, base, ng, cg, lane,
                g_stats + layer * 256, g_stats + layer * 256 + 64);
}

// ======== kB: BN1+ReLU -> smem(T) -> tiled GEMM2 -> z2 + stats2 =================
__global__ void __launch_bounds__(256) kB(const float* __restrict__ W,
                                          const float* __restrict__ b,
                                          const float* __restrict__ gam,
                                          const float* __restrict__ bet, int layer) {
    __shared__ float y_s[64 * PAD];
    __shared__ float Wsh[4096];
    __shared__ float bs[64], sA[64], sB[64];
    int tid = threadIdx.x, lane = tid & 31, wid = tid >> 5;
    for (int i = tid; i < 4096; i += 256) Wsh[i] = W[i];
    if (tid < 64) {
        float s = g_stats[layer * 256 + tid];
        float q = g_stats[layer * 256 + 64 + tid];
        float mu = s * (1.f / NN);
        float var = q * (1.f / NN) - mu * mu;
        float a = rsqrtf(var + 1e-5f) * gam[tid];
        sA[tid] = a;
        sB[tid] = bet[tid] - mu * a;
        bs[tid] = b[tid];
    }
    __syncthreads();
    int base = blockIdx.x * NPB;

#pragma unroll 2
    for (int i = 0; i < 8; i++) {
        int nl = wid * 8 + i;
        int n = base + nl;
        float yx = 0.f, yy = 0.f;
        if (n < NN) {
            float2 v = ((const float2*)(g_z1 + (size_t)n * 64))[lane];
            int k0 = 2 * lane;
            yx = fmaxf(fmaf(v.x, sA[k0], sB[k0]), 0.f);
            yy = fmaxf(fmaf(v.y, sA[k0 + 1], sB[k0 + 1]), 0.f);
        }
        y_s[(2 * lane) * PAD + nl] = yx;
        y_s[(2 * lane + 1) * PAD + nl] = yy;
    }
    __syncthreads();

    int ng = tid & 15, cg = tid >> 4;
    ull acc[4][2];
    gemm_tile(y_s, Wsh, bs, cg, ng, acc);
    store_stats(acc, g_z2, base, ng, cg, lane,
                g_stats + layer * 256 + 128, g_stats + layer * 256 + 192);
}

// ======== kC: BN2+ReLU -> h; logits += h @ fcW[layer+1]; optional softmax =======
__global__ void __launch_bounds__(256) kC(const float* __restrict__ gam,
                                          const float* __restrict__ bet,
                                          const float* __restrict__ fcW,
                                          int layer, int final_layer,
                                          float* __restrict__ out) {
    __shared__ float fw[640];
    __shared__ float sA[64], sB[64];
    int tid = threadIdx.x;
    const float* fsrc = fcW + (layer + 1) * 640;
    for (int i = tid; i < 640; i += 256) fw[i] = fsrc[i];
    if (tid < 64) {
        float s = g_stats[layer * 256 + 128 + tid];
        float q = g_stats[layer * 256 + 192 + tid];
        float mu = s * (1.f / NN);
        float var = q * (1.f / NN) - mu * mu;
        float a = rsqrtf(var + 1e-5f) * gam[tid];
        sA[tid] = a;
        sB[tid] = bet[tid] - mu * a;
    }
    __syncthreads();
    int n = blockIdx.x * 256 + tid;
    if (n >= NN) return;
    float o[10];
#pragma unroll
    for (int c = 0; c < 10; c++) o[c] = out[n * 10 + c];
    const float4* z4 = ((const float4*)g_z2) + (size_t)n * 16;
    float4* hout = ((float4*)g_h) + (size_t)n * 16;
#pragma unroll
    for (int kk = 0; kk < 16; kk++) {
        float4 v = z4[kk];
        int k0 = kk * 4;
        float h0 = fmaxf(fmaf(v.x, sA[k0 + 0], sB[k0 + 0]), 0.f);
        float h1 = fmaxf(fmaf(v.y, sA[k0 + 1], sB[k0 + 1]), 0.f);
        float h2 = fmaxf(fmaf(v.z, sA[k0 + 2], sB[k0 + 2]), 0.f);
        float h3 = fmaxf(fmaf(v.w, sA[k0 + 3], sB[k0 + 3]), 0.f);
        if (!final_layer) hout[kk] = make_float4(h0, h1, h2, h3);
        const float* r0 = fw + k0 * 10;
#pragma unroll
        for (int c = 0; c < 10; c++)
            o[c] += h0 * r0[c] + h1 * r0[10 + c] + h2 * r0[20 + c] + h3 * r0[30 + c];
    }
    if (final_layer) {
        float m = -1e30f;
#pragma unroll
        for (int c = 0; c < 10; c++) m = fmaxf(m, o[c]);
        float s = 0.f;
#pragma unroll
        for (int c = 0; c < 10; c++) s += expf(o[c] - m);
        float lse = m + logf(s);
#pragma unroll
        for (int c = 0; c < 10; c++) o[c] -= lse;
    }
#pragma unroll
    for (int c = 0; c < 10; c++) out[n * 10 + c] = o[c];
}

// ---------------- launch --------------------------------------------------------
extern "C" void kernel_launch(void* const* d_in, const int* in_sizes, int n_in,
                              void* d_out, int out_size) {
    const float* x   = (const float*)d_in[0];
    const int*   ei  = (const int*)d_in[1];
    const float* W1  = (const float*)d_in[2];
    const float* b1  = (const float*)d_in[3];
    const float* g1  = (const float*)d_in[4];
    const float* be1 = (const float*)d_in[5];
    const float* W2  = (const float*)d_in[6];
    const float* b2  = (const float*)d_in[7];
    const float* gbn = (const float*)d_in[8];
    const float* bbn = (const float*)d_in[9];
    const float* fcW = (const float*)d_in[10];
    const float* fcb = (const float*)d_in[11];
    float* out = (float*)d_out;

    const int AB = (NN + NPB - 1) / NPB;  // 1563
    const int CB = (NN + 255) / 256;      // 391

    kzero<<<(NN + 1023) / 1024, 1024>>>();
    kfill<<<(EE + 255) / 256, 256>>>(ei);
    kinit<<<CB, 256>>>(x, fcW, fcb, out);
    for (int l = 0; l < LL; l++) {
        int use_x = (l == 0) ? 1 : 0;
        kA<<<AB, 256>>>(x, use_x, W1 + l * 4096, b1 + l * 64, l);
        kB<<<AB, 256>>>(W2 + l * 4096, b2 + l * 64, g1 + l * 64, be1 + l * 64, l);
        kC<<<CB, 256>>>(gbn + l * 64, bbn + l * 64, fcW, l, (l == LL - 1) ? 1 : 0, out);
    }
}